// round 14
// baseline (speedup 1.0000x reference)
#include <cuda_runtime.h>
#include <cuda_fp16.h>
#include <math.h>

#define NODES 100000
#define EDGES_MAX 1600000
#define FEAT  128
#define SCAN_B 256
#define NBLK_SCAN ((NODES + SCAN_B - 1) / SCAN_B)   // 391

// Scratch: __device__ globals (allocation-free rule). Device-side use only.
__device__ __half g_half[NODES * FEAT];  // g = (in @ W) * dinv  (agg gather src)
__device__ __half g_h2[NODES * FEAT];    // layer-1 output h (GEMM-2 input)
__device__ __half g_w1h[FEAT * FEAT];    // fp16 W1
__device__ __half g_w2h[FEAT * FEAT];    // fp16 W2
__device__ int    g_cnt[NODES];
__device__ int    g_incl[NODES];
__device__ int    g_rowstart[NODES];
__device__ int    g_cur[NODES];
__device__ int    g_poff[NBLK_SCAN + 1];
__device__ int    g_csr[EDGES_MAX];
__device__ int    g_idx64;

// ---------------------------------------------------------------------------
// init: zero histogram, detect edge dtype, convert W1/W2 to fp16.
// ---------------------------------------------------------------------------
__global__ void k_init(const void* __restrict__ ei,
                       const float* __restrict__ W1,
                       const float* __restrict__ W2, int n) {
    int i = blockIdx.x * blockDim.x + threadIdx.x;
    if (i < n) g_cnt[i] = 0;
    if (i < 8192) {
        const float4* src = (i < 4096) ? (const float4*)W1 : (const float4*)W2;
        uint2* dst = (i < 4096) ? (uint2*)g_w1h : (uint2*)g_w2h;
        int off = i & 4095;
        float4 v = src[off];
        uint2 d;
        *(__half2*)&d.x = __floats2half2_rn(v.x, v.y);
        *(__half2*)&d.y = __floats2half2_rn(v.z, v.w);
        dst[off] = d;
    }
    if (blockIdx.x == 0) {
        __shared__ int ok;
        if (threadIdx.x == 0) ok = 1;
        __syncthreads();
        long long v = ((const long long*)ei)[threadIdx.x];
        if (v < 0 || v >= NODES) ok = 0;
        __syncthreads();
        if (threadIdx.x == 0) g_idx64 = ok;
    }
}

__device__ __forceinline__ int load_idx(const void* ei, long long elem) {
    if (g_idx64) return (int)((const long long*)ei)[elem];
    return ((const int*)ei)[elem];
}

// ---------------------------------------------------------------------------
__global__ void k_hist(const void* __restrict__ ei, int E) {
    int e = blockIdx.x * blockDim.x + threadIdx.x;
    if (e >= E) return;
    int d = load_idx(ei, (long long)E + e);
    if ((unsigned)d < NODES) atomicAdd(&g_cnt[d], 1);
}

// ---------------------------------------------------------------------------
// CSR scans + placement
// ---------------------------------------------------------------------------
__global__ void k_scan1(int n) {
    __shared__ int sm[SCAN_B];
    int i = blockIdx.x * SCAN_B + threadIdx.x;
    int v = (i < n) ? g_cnt[i] : 0;
    sm[threadIdx.x] = v;
    __syncthreads();
#pragma unroll
    for (int o = 1; o < SCAN_B; o <<= 1) {
        int t = (threadIdx.x >= o) ? sm[threadIdx.x - o] : 0;
        __syncthreads();
        sm[threadIdx.x] += t;
        __syncthreads();
    }
    if (i < n) g_incl[i] = sm[threadIdx.x];
    if (threadIdx.x == SCAN_B - 1) g_poff[blockIdx.x] = sm[SCAN_B - 1];
}

__global__ void k_scan2() {
    __shared__ int sm[512];
    int i = threadIdx.x;
    int v = (i < NBLK_SCAN) ? g_poff[i] : 0;
    sm[i] = v;
    __syncthreads();
#pragma unroll
    for (int o = 1; o < 512; o <<= 1) {
        int t = (i >= o) ? sm[i - o] : 0;
        __syncthreads();
        sm[i] += t;
        __syncthreads();
    }
    if (i < NBLK_SCAN) g_poff[i] = sm[i] - v;   // exclusive
}

__global__ void k_scan3(int n) {
    int i = blockIdx.x * blockDim.x + threadIdx.x;
    if (i >= n) return;
    int c = g_cnt[i];
    int rs = g_incl[i] - c + g_poff[i >> 8];
    g_rowstart[i] = rs;
    g_cur[i] = rs;
}

__global__ void k_place(const void* __restrict__ ei, int E) {
    int e = blockIdx.x * blockDim.x + threadIdx.x;
    if (e >= E) return;
    int s = load_idx(ei, e);
    int d = load_idx(ei, (long long)E + e);
    if ((unsigned)s >= NODES || (unsigned)d >= NODES) return;
    int pos = atomicAdd(&g_cur[d], 1);
    g_csr[pos] = s;
}

// ---------------------------------------------------------------------------
#define SROW 136   // half stride (272 B): conflict-free ldmatrix

__device__ __forceinline__ void add_row(float4& acc, uint2 v) {
    float2 p0 = __half22float2(*(__half2*)&v.x);
    float2 p1 = __half22float2(*(__half2*)&v.y);
    acc.x += p0.x; acc.y += p0.y; acc.z += p1.x; acc.w += p1.y;
}

// Warp-collective: aggregate one node's CSR row from src (fp16, 8B/lane).
// CSR indices read via int4 (alignment fixed by scalar prologue).
__device__ __forceinline__ float4 gather_node(const uint2* __restrict__ src,
                                              int node, int q) {
    int base = g_rowstart[node];
    int cnt  = g_cnt[node];
    int end  = base + cnt;
    float4 acc = make_float4(0.f, 0.f, 0.f, 0.f);
    add_row(acc, src[node * 32 + q]);          // self-loop term

    int e = base;
    // scalar prologue to 16B-align the index pointer
    int pre = (4 - (base & 3)) & 3;
    if (pre > cnt) pre = cnt;
    for (int i = 0; i < pre; i++, e++)
        add_row(acc, src[g_csr[e] * 32 + q]);

    for (; e + 8 <= end; e += 8) {
        int4 c0 = *(const int4*)&g_csr[e];
        int4 c1 = *(const int4*)&g_csr[e + 4];
        uint2 v0 = src[c0.x * 32 + q];
        uint2 v1 = src[c0.y * 32 + q];
        uint2 v2 = src[c0.z * 32 + q];
        uint2 v3 = src[c0.w * 32 + q];
        uint2 v4 = src[c1.x * 32 + q];
        uint2 v5 = src[c1.y * 32 + q];
        uint2 v6 = src[c1.z * 32 + q];
        uint2 v7 = src[c1.w * 32 + q];
        add_row(acc, v0); add_row(acc, v1); add_row(acc, v2); add_row(acc, v3);
        add_row(acc, v4); add_row(acc, v5); add_row(acc, v6); add_row(acc, v7);
    }
    if (e + 4 <= end) {
        int4 c0 = *(const int4*)&g_csr[e];
        uint2 v0 = src[c0.x * 32 + q];
        uint2 v1 = src[c0.y * 32 + q];
        uint2 v2 = src[c0.z * 32 + q];
        uint2 v3 = src[c0.w * 32 + q];
        add_row(acc, v0); add_row(acc, v1); add_row(acc, v2); add_row(acc, v3);
        e += 4;
    }
    for (; e < end; e++)
        add_row(acc, src[g_csr[e] * 32 + q]);
    return acc;
}

// ---------------------------------------------------------------------------
// fp16 GEMM, full-K single tile:
//   g_half[row][c] = fp16( (sum_k A[row][k] * W[k][c]) * rsqrt(cnt[row]+1) )
// use_h=0: A from fp32 x (LDG+cvt+STS), W1 via cp.async.
// use_h=1: A=g_h2 via cp.async (two k-split commit groups), W2.
// ---------------------------------------------------------------------------
__global__ void __launch_bounds__(256)
k_gemm_f16(const float* __restrict__ x, int n, int use_h) {
    extern __shared__ __half smem[];
    __half* As = smem;
    __half* Ws = smem + 128 * SROW;

    int tid  = threadIdx.x;
    int wid  = tid >> 5;
    int lane = tid & 31;
    int gq   = lane >> 2;
    int tq   = lane & 3;
    int warp_m = wid & 1;
    int warp_n = wid >> 1;
    int row0 = blockIdx.x * 128;

    const __half* Wg = use_h ? g_w2h : g_w1h;

    float acc[4][4][4];
#pragma unroll
    for (int mt = 0; mt < 4; mt++)
#pragma unroll
        for (int j = 0; j < 4; j++)
#pragma unroll
            for (int r = 0; r < 4; r++) acc[mt][j][r] = 0.f;

    unsigned a_base[4], b_base[2];
    {
        int arow = lane & 15;
        int akof = ((lane >> 4) & 1) * 8;
#pragma unroll
        for (int mt = 0; mt < 4; mt++)
            a_base[mt] = (unsigned)__cvta_generic_to_shared(
                &As[(warp_m * 64 + mt * 16 + arow) * SROW + akof]);
        int nof = ((lane >> 4) & 1) * 8;
#pragma unroll
        for (int nt2 = 0; nt2 < 2; nt2++)
            b_base[nt2] = (unsigned)__cvta_generic_to_shared(
                &Ws[(lane & 15) * SROW + warp_n * 32 + nt2 * 16 + nof]);
    }

    if (!use_h) {
#pragma unroll
        for (int i = 0; i < 8; i++) {
            int slot = tid + i * 256;
            int r   = slot >> 4;
            int c16 = slot & 15;
            unsigned dw = (unsigned)__cvta_generic_to_shared(&Ws[r * SROW + c16 * 8]);
            asm volatile("cp.async.ca.shared.global [%0], [%1], 16;"
                         :: "r"(dw), "l"(Wg + r * 128 + c16 * 8));
        }
        asm volatile("cp.async.commit_group;");

        const float4* X4 = (const float4*)x;
#pragma unroll
        for (int i = 0; i < 8; i++) {
            int slot = tid + i * 256;
            int r   = slot >> 4;
            int c16 = slot & 15;
            int gr = row0 + r;
            float4 v0 = make_float4(0.f, 0.f, 0.f, 0.f);
            float4 v1 = v0;
            if (gr < n) {
                v0 = X4[(long long)gr * 32 + c16 * 2];
                v1 = X4[(long long)gr * 32 + c16 * 2 + 1];
            }
            uint4 d;
            *(__half2*)&d.x = __floats2half2_rn(v0.x, v0.y);
            *(__half2*)&d.y = __floats2half2_rn(v0.z, v0.w);
            *(__half2*)&d.z = __floats2half2_rn(v1.x, v1.y);
            *(__half2*)&d.w = __floats2half2_rn(v1.z, v1.w);
            *(uint4*)&As[r * SROW + c16 * 8] = d;
        }
        asm volatile("cp.async.wait_group 0;");
        __syncthreads();

#pragma unroll
        for (int ks = 0; ks < 8; ks++) {
            unsigned a[4][4], b[2][4];
#pragma unroll
            for (int mt = 0; mt < 4; mt++)
                asm volatile(
                    "ldmatrix.sync.aligned.m8n8.x4.shared.b16 {%0,%1,%2,%3}, [%4];"
                    : "=r"(a[mt][0]), "=r"(a[mt][1]), "=r"(a[mt][2]), "=r"(a[mt][3])
                    : "r"(a_base[mt] + ks * 32));
#pragma unroll
            for (int nt2 = 0; nt2 < 2; nt2++)
                asm volatile(
                    "ldmatrix.sync.aligned.m8n8.x4.trans.shared.b16 {%0,%1,%2,%3}, [%4];"
                    : "=r"(b[nt2][0]), "=r"(b[nt2][1]), "=r"(b[nt2][2]), "=r"(b[nt2][3])
                    : "r"(b_base[nt2] + ks * 16 * SROW * 2));
#pragma unroll
            for (int nt2 = 0; nt2 < 2; nt2++)
#pragma unroll
                for (int h8 = 0; h8 < 2; h8++) {
                    int j = nt2 * 2 + h8;
#pragma unroll
                    for (int mt = 0; mt < 4; mt++)
                        asm volatile(
                            "mma.sync.aligned.m16n8k16.row.col.f32.f16.f16.f32 "
                            "{%0,%1,%2,%3}, {%4,%5,%6,%7}, {%8,%9}, {%0,%1,%2,%3};"
                            : "+f"(acc[mt][j][0]), "+f"(acc[mt][j][1]),
                              "+f"(acc[mt][j][2]), "+f"(acc[mt][j][3])
                            : "r"(a[mt][0]), "r"(a[mt][1]),
                              "r"(a[mt][2]), "r"(a[mt][3]),
                              "r"(b[nt2][h8 * 2]), "r"(b[nt2][h8 * 2 + 1]));
                }
        }
    } else {
        const __half* Ag = g_h2;
#pragma unroll
        for (int grp = 0; grp < 2; grp++) {
#pragma unroll
            for (int i = 0; i < 4; i++) {
                int slot = tid + i * 256;       // 0..1023
                int r   = slot >> 3;            // 0..127
                int c16 = (slot & 7) + grp * 8;
                unsigned da = (unsigned)__cvta_generic_to_shared(&As[r * SROW + c16 * 8]);
                const __half* sa = Ag + (long long)(row0 + r) * 128 + c16 * 8;
                int va = (row0 + r < n) ? 16 : 0;
                asm volatile("cp.async.ca.shared.global [%0], [%1], 16, %2;"
                             :: "r"(da), "l"(sa), "r"(va));
                int wrow = grp * 64 + (slot >> 4);
                int wchk = slot & 15;
                unsigned dw = (unsigned)__cvta_generic_to_shared(&Ws[wrow * SROW + wchk * 8]);
                asm volatile("cp.async.ca.shared.global [%0], [%1], 16;"
                             :: "r"(dw), "l"(Wg + wrow * 128 + wchk * 8));
            }
            asm volatile("cp.async.commit_group;");
        }

        asm volatile("cp.async.wait_group 1;");
        __syncthreads();
#pragma unroll
        for (int ks = 0; ks < 4; ks++) {
            unsigned a[4][4], b[2][4];
#pragma unroll
            for (int mt = 0; mt < 4; mt++)
                asm volatile(
                    "ldmatrix.sync.aligned.m8n8.x4.shared.b16 {%0,%1,%2,%3}, [%4];"
                    : "=r"(a[mt][0]), "=r"(a[mt][1]), "=r"(a[mt][2]), "=r"(a[mt][3])
                    : "r"(a_base[mt] + ks * 32));
#pragma unroll
            for (int nt2 = 0; nt2 < 2; nt2++)
                asm volatile(
                    "ldmatrix.sync.aligned.m8n8.x4.trans.shared.b16 {%0,%1,%2,%3}, [%4];"
                    : "=r"(b[nt2][0]), "=r"(b[nt2][1]), "=r"(b[nt2][2]), "=r"(b[nt2][3])
                    : "r"(b_base[nt2] + ks * 16 * SROW * 2));
#pragma unroll
            for (int nt2 = 0; nt2 < 2; nt2++)
#pragma unroll
                for (int h8 = 0; h8 < 2; h8++) {
                    int j = nt2 * 2 + h8;
#pragma unroll
                    for (int mt = 0; mt < 4; mt++)
                        asm volatile(
                            "mma.sync.aligned.m16n8k16.row.col.f32.f16.f16.f32 "
                            "{%0,%1,%2,%3}, {%4,%5,%6,%7}, {%8,%9}, {%0,%1,%2,%3};"
                            : "+f"(acc[mt][j][0]), "+f"(acc[mt][j][1]),
                              "+f"(acc[mt][j][2]), "+f"(acc[mt][j][3])
                            : "r"(a[mt][0]), "r"(a[mt][1]),
                              "r"(a[mt][2]), "r"(a[mt][3]),
                              "r"(b[nt2][h8 * 2]), "r"(b[nt2][h8 * 2 + 1]));
                }
        }
        asm volatile("cp.async.wait_group 0;");
        __syncthreads();
#pragma unroll
        for (int ks = 4; ks < 8; ks++) {
            unsigned a[4][4], b[2][4];
#pragma unroll
            for (int mt = 0; mt < 4; mt++)
                asm volatile(
                    "ldmatrix.sync.aligned.m8n8.x4.shared.b16 {%0,%1,%2,%3}, [%4];"
                    : "=r"(a[mt][0]), "=r"(a[mt][1]), "=r"(a[mt][2]), "=r"(a[mt][3])
                    : "r"(a_base[mt] + ks * 32));
#pragma unroll
            for (int nt2 = 0; nt2 < 2; nt2++)
                asm volatile(
                    "ldmatrix.sync.aligned.m8n8.x4.trans.shared.b16 {%0,%1,%2,%3}, [%4];"
                    : "=r"(b[nt2][0]), "=r"(b[nt2][1]), "=r"(b[nt2][2]), "=r"(b[nt2][3])
                    : "r"(b_base[nt2] + ks * 16 * SROW * 2));
#pragma unroll
            for (int nt2 = 0; nt2 < 2; nt2++)
#pragma unroll
                for (int h8 = 0; h8 < 2; h8++) {
                    int j = nt2 * 2 + h8;
#pragma unroll
                    for (int mt = 0; mt < 4; mt++)
                        asm volatile(
                            "mma.sync.aligned.m16n8k16.row.col.f32.f16.f16.f32 "
                            "{%0,%1,%2,%3}, {%4,%5,%6,%7}, {%8,%9}, {%0,%1,%2,%3};"
                            : "+f"(acc[mt][j][0]), "+f"(acc[mt][j][1]),
                              "+f"(acc[mt][j][2]), "+f"(acc[mt][j][3])
                            : "r"(a[mt][0]), "r"(a[mt][1]),
                              "r"(a[mt][2]), "r"(a[mt][3]),
                              "r"(b[nt2][h8 * 2]), "r"(b[nt2][h8 * 2 + 1]));
                }
        }
    }

    // epilogue: dinv = rsqrt(cnt+1), convert to fp16, write g_half
#pragma unroll
    for (int mt = 0; mt < 4; mt++) {
        int rlo = row0 + warp_m * 64 + mt * 16 + gq;
        int rhi = rlo + 8;
        float dlo = (rlo < n) ? rsqrtf((float)g_cnt[rlo] + 1.0f) : 0.f;
        float dhi = (rhi < n) ? rsqrtf((float)g_cnt[rhi] + 1.0f) : 0.f;
#pragma unroll
        for (int j = 0; j < 4; j++) {
            int c = warp_n * 32 + j * 8 + 2 * tq;
            if (rlo < n)
                *(__half2*)&g_half[rlo * 128 + c] =
                    __floats2half2_rn(acc[mt][j][0] * dlo, acc[mt][j][1] * dlo);
            if (rhi < n)
                *(__half2*)&g_half[rhi * 128 + c] =
                    __floats2half2_rn(acc[mt][j][2] * dhi, acc[mt][j][3] * dhi);
        }
    }
}

// ---------------------------------------------------------------------------
// Aggregate (warp per node):
//   FINAL=0: h=relu(dinv*acc+b) -> g_h2 (fp16)
//   FINAL=1: fused FC + log_softmax -> out
// ---------------------------------------------------------------------------
template <int FINAL>
__global__ void k_agg(const float* __restrict__ b,
                      const float* __restrict__ Wfc,
                      const float* __restrict__ bfc,
                      float* __restrict__ out,
                      int n) {
    int widx = (blockIdx.x * blockDim.x + threadIdx.x) >> 5;
    int q = threadIdx.x & 31;
    if (widx >= n) return;

    float4 acc = gather_node((const uint2*)g_half, widx, q);

    float dv = rsqrtf((float)g_cnt[widx] + 1.0f);
    float4 bb = ((const float4*)b)[q];
    float4 h;
    h.x = fmaxf(dv * acc.x + bb.x, 0.f);
    h.y = fmaxf(dv * acc.y + bb.y, 0.f);
    h.z = fmaxf(dv * acc.z + bb.z, 0.f);
    h.w = fmaxf(dv * acc.w + bb.w, 0.f);

    if (!FINAL) {
        uint2 st;
        *(__half2*)&st.x = __floats2half2_rn(h.x, h.y);
        *(__half2*)&st.y = __floats2half2_rn(h.z, h.w);
        ((uint2*)g_h2)[widx * 32 + q] = st;
    } else {
        const float4* w4 = (const float4*)Wfc;
        float4 w0 = w4[q * 2];
        float4 w1 = w4[q * 2 + 1];
        float l0 = h.x * w0.x + h.y * w0.z + h.z * w1.x + h.w * w1.z;
        float l1 = h.x * w0.y + h.y * w0.w + h.z * w1.y + h.w * w1.w;
#pragma unroll
        for (int o = 16; o > 0; o >>= 1) {
            l0 += __shfl_xor_sync(0xffffffffu, l0, o);
            l1 += __shfl_xor_sync(0xffffffffu, l1, o);
        }
        if (q == 0) {
            l0 += bfc[0];
            l1 += bfc[1];
            float m = fmaxf(l0, l1);
            float z = m + logf(expf(l0 - m) + expf(l1 - m));
            out[widx * 2]     = l0 - z;
            out[widx * 2 + 1] = l1 - z;
        }
    }
}

// ---------------------------------------------------------------------------
extern "C" void kernel_launch(void* const* d_in, const int* in_sizes, int n_in,
                              void* d_out, int out_size) {
    const float* x   = (const float*)d_in[0];
    const void*  ei  = d_in[1];
    const float* W1  = (const float*)d_in[2];
    const float* b1  = (const float*)d_in[3];
    const float* W2  = (const float*)d_in[4];
    const float* b2  = (const float*)d_in[5];
    const float* Wfc = (const float*)d_in[6];
    const float* bfc = (const float*)d_in[7];
    float*       out = (float*)d_out;

    int n = in_sizes[0] / FEAT;
    int E = in_sizes[1] / 2;

    int tb = 256;
    int node_blocks = (n + tb - 1) / tb;
    int edge_blocks = (E + tb - 1) / tb;
    int gemm_blocks = (n + 127) / 128;
    int warp_blocks = (int)(((long long)n * 32 + tb - 1) / tb);

    static int once = 0;
    static cudaStream_t s2;
    static cudaEvent_t ev_fork, ev_join;
    int gemm_smem = 2 * 128 * SROW * (int)sizeof(__half);   // 69632
    if (!once) {
        cudaFuncSetAttribute(k_gemm_f16,
                             cudaFuncAttributeMaxDynamicSharedMemorySize, gemm_smem);
        cudaStreamCreateWithFlags(&s2, cudaStreamNonBlocking);
        cudaEventCreateWithFlags(&ev_fork, cudaEventDisableTiming);
        cudaEventCreateWithFlags(&ev_join, cudaEventDisableTiming);
        once = 1;
    }

    // main stream: init (cnt zero + dtype + W fp16) + histogram
    k_init<<<node_blocks, tb>>>(ei, W1, W2, n);
    k_hist<<<edge_blocks, tb>>>(ei, E);

    // fork: CSR finalize on s2, concurrent with layer-1 GEMM
    cudaEventRecord(ev_fork, 0);
    cudaStreamWaitEvent(s2, ev_fork, 0);
    k_scan1<<<NBLK_SCAN, SCAN_B, 0, s2>>>(n);
    k_scan2<<<1, 512, 0, s2>>>();
    k_scan3<<<node_blocks, tb, 0, s2>>>(n);
    k_place<<<edge_blocks, tb, 0, s2>>>(ei, E);
    cudaEventRecord(ev_join, s2);

    // main: layer-1 GEMM (needs g_cnt + g_w1h)
    k_gemm_f16<<<gemm_blocks, tb, gemm_smem>>>(x, n, 0);

    // join: aggregate needs both CSR and g_half
    cudaStreamWaitEvent(0, ev_join, 0);
    k_agg<0><<<warp_blocks, tb>>>(b1, nullptr, nullptr, nullptr, n);

    // layer 2 + fused FC/log_softmax
    k_gemm_f16<<<gemm_blocks, tb, gemm_smem>>>(x, n, 1);
    k_agg<1><<<warp_blocks, tb>>>(b2, Wfc, bfc, out, n);
}

// round 15
// speedup vs baseline: 1.5023x; 1.5023x over previous
#include <cuda_runtime.h>
#include <cuda_fp16.h>
#include <math.h>

#define NODES 100000
#define EDGES_MAX 1600000
#define FEAT  128
#define SCAN_B 256
#define NBLK_SCAN ((NODES + SCAN_B - 1) / SCAN_B)   // 391

// Scratch: __device__ globals (allocation-free rule). Device-side use only.
__device__ __half g_half[NODES * FEAT];  // g = (in @ W) * dinv  (agg gather src)
__device__ __half g_h2[NODES * FEAT];    // layer-1 output h (GEMM-2 input)
__device__ __half g_w1h[FEAT * FEAT];    // fp16 W1
__device__ __half g_w2h[FEAT * FEAT];    // fp16 W2
__device__ int    g_cnt[NODES];
__device__ int    g_incl[NODES];
__device__ int    g_rowstart[NODES];
__device__ int    g_cur[NODES];
__device__ int    g_poff[NBLK_SCAN + 1];
__device__ int    g_csr[EDGES_MAX];
__device__ int    g_idx64;

// ---------------------------------------------------------------------------
// init: zero histogram, detect edge dtype, convert W1/W2 to fp16.
// ---------------------------------------------------------------------------
__global__ void k_init(const void* __restrict__ ei,
                       const float* __restrict__ W1,
                       const float* __restrict__ W2, int n) {
    int i = blockIdx.x * blockDim.x + threadIdx.x;
    if (i < n) g_cnt[i] = 0;
    if (i < 8192) {
        const float4* src = (i < 4096) ? (const float4*)W1 : (const float4*)W2;
        uint2* dst = (i < 4096) ? (uint2*)g_w1h : (uint2*)g_w2h;
        int off = i & 4095;
        float4 v = src[off];
        uint2 d;
        *(__half2*)&d.x = __floats2half2_rn(v.x, v.y);
        *(__half2*)&d.y = __floats2half2_rn(v.z, v.w);
        dst[off] = d;
    }
    if (blockIdx.x == 0) {
        __shared__ int ok;
        if (threadIdx.x == 0) ok = 1;
        __syncthreads();
        long long v = ((const long long*)ei)[threadIdx.x];
        if (v < 0 || v >= NODES) ok = 0;
        __syncthreads();
        if (threadIdx.x == 0) g_idx64 = ok;
    }
}

__device__ __forceinline__ int load_idx(const void* ei, long long elem) {
    if (g_idx64) return (int)((const long long*)ei)[elem];
    return ((const int*)ei)[elem];
}

// ---------------------------------------------------------------------------
__global__ void k_hist(const void* __restrict__ ei, int E) {
    int e = blockIdx.x * blockDim.x + threadIdx.x;
    if (e >= E) return;
    int d = load_idx(ei, (long long)E + e);
    if ((unsigned)d < NODES) atomicAdd(&g_cnt[d], 1);
}

// ---------------------------------------------------------------------------
// CSR scans + placement
// ---------------------------------------------------------------------------
__global__ void k_scan1(int n) {
    __shared__ int sm[SCAN_B];
    int i = blockIdx.x * SCAN_B + threadIdx.x;
    int v = (i < n) ? g_cnt[i] : 0;
    sm[threadIdx.x] = v;
    __syncthreads();
#pragma unroll
    for (int o = 1; o < SCAN_B; o <<= 1) {
        int t = (threadIdx.x >= o) ? sm[threadIdx.x - o] : 0;
        __syncthreads();
        sm[threadIdx.x] += t;
        __syncthreads();
    }
    if (i < n) g_incl[i] = sm[threadIdx.x];
    if (threadIdx.x == SCAN_B - 1) g_poff[blockIdx.x] = sm[SCAN_B - 1];
}

__global__ void k_scan2() {
    __shared__ int sm[512];
    int i = threadIdx.x;
    int v = (i < NBLK_SCAN) ? g_poff[i] : 0;
    sm[i] = v;
    __syncthreads();
#pragma unroll
    for (int o = 1; o < 512; o <<= 1) {
        int t = (i >= o) ? sm[i - o] : 0;
        __syncthreads();
        sm[i] += t;
        __syncthreads();
    }
    if (i < NBLK_SCAN) g_poff[i] = sm[i] - v;   // exclusive
}

__global__ void k_scan3(int n) {
    int i = blockIdx.x * blockDim.x + threadIdx.x;
    if (i >= n) return;
    int c = g_cnt[i];
    int rs = g_incl[i] - c + g_poff[i >> 8];
    g_rowstart[i] = rs;
    g_cur[i] = rs;
}

__global__ void k_place(const void* __restrict__ ei, int E) {
    int e = blockIdx.x * blockDim.x + threadIdx.x;
    if (e >= E) return;
    int s = load_idx(ei, e);
    int d = load_idx(ei, (long long)E + e);
    if ((unsigned)s >= NODES || (unsigned)d >= NODES) return;
    int pos = atomicAdd(&g_cur[d], 1);
    g_csr[pos] = s;
}

// ---------------------------------------------------------------------------
#define SROW 136   // half stride (272 B): conflict-free ldmatrix

__device__ __forceinline__ void add_row(float4& acc, uint2 v) {
    float2 p0 = __half22float2(*(__half2*)&v.x);
    float2 p1 = __half22float2(*(__half2*)&v.y);
    acc.x += p0.x; acc.y += p0.y; acc.z += p1.x; acc.w += p1.y;
}

// Warp-collective: aggregate one node's CSR row from src (fp16, 8B/lane).
// Scalar (warp-uniform broadcast) index loads — measured best shape.
__device__ __forceinline__ float4 gather_node(const uint2* __restrict__ src,
                                              int node, int q) {
    int base = g_rowstart[node];
    int end  = base + g_cnt[node];
    float4 acc = make_float4(0.f, 0.f, 0.f, 0.f);
    add_row(acc, src[node * 32 + q]);          // self-loop term
    int e = base;
    for (; e + 8 <= end; e += 8) {
        uint2 v0 = src[g_csr[e]     * 32 + q];
        uint2 v1 = src[g_csr[e + 1] * 32 + q];
        uint2 v2 = src[g_csr[e + 2] * 32 + q];
        uint2 v3 = src[g_csr[e + 3] * 32 + q];
        uint2 v4 = src[g_csr[e + 4] * 32 + q];
        uint2 v5 = src[g_csr[e + 5] * 32 + q];
        uint2 v6 = src[g_csr[e + 6] * 32 + q];
        uint2 v7 = src[g_csr[e + 7] * 32 + q];
        add_row(acc, v0); add_row(acc, v1); add_row(acc, v2); add_row(acc, v3);
        add_row(acc, v4); add_row(acc, v5); add_row(acc, v6); add_row(acc, v7);
    }
    for (; e + 2 <= end; e += 2) {
        uint2 v0 = src[g_csr[e]     * 32 + q];
        uint2 v1 = src[g_csr[e + 1] * 32 + q];
        add_row(acc, v0); add_row(acc, v1);
    }
    if (e < end) add_row(acc, src[g_csr[e] * 32 + q]);
    return acc;
}

// ---------------------------------------------------------------------------
// fp16 GEMM, full-K single tile:
//   g_half[row][c] = fp16( (sum_k A[row][k] * W[k][c]) * rsqrt(cnt[row]+1) )
// use_h=0: A from fp32 x (LDG+cvt+STS), W1 via cp.async.
// use_h=1: A=g_h2 via cp.async (two k-split commit groups), W2.
// ---------------------------------------------------------------------------
__global__ void __launch_bounds__(256)
k_gemm_f16(const float* __restrict__ x, int n, int use_h) {
    extern __shared__ __half smem[];
    __half* As = smem;
    __half* Ws = smem + 128 * SROW;

    int tid  = threadIdx.x;
    int wid  = tid >> 5;
    int lane = tid & 31;
    int gq   = lane >> 2;
    int tq   = lane & 3;
    int warp_m = wid & 1;
    int warp_n = wid >> 1;
    int row0 = blockIdx.x * 128;

    const __half* Wg = use_h ? g_w2h : g_w1h;

    float acc[4][4][4];
#pragma unroll
    for (int mt = 0; mt < 4; mt++)
#pragma unroll
        for (int j = 0; j < 4; j++)
#pragma unroll
            for (int r = 0; r < 4; r++) acc[mt][j][r] = 0.f;

    unsigned a_base[4], b_base[2];
    {
        int arow = lane & 15;
        int akof = ((lane >> 4) & 1) * 8;
#pragma unroll
        for (int mt = 0; mt < 4; mt++)
            a_base[mt] = (unsigned)__cvta_generic_to_shared(
                &As[(warp_m * 64 + mt * 16 + arow) * SROW + akof]);
        int nof = ((lane >> 4) & 1) * 8;
#pragma unroll
        for (int nt2 = 0; nt2 < 2; nt2++)
            b_base[nt2] = (unsigned)__cvta_generic_to_shared(
                &Ws[(lane & 15) * SROW + warp_n * 32 + nt2 * 16 + nof]);
    }

    if (!use_h) {
#pragma unroll
        for (int i = 0; i < 8; i++) {
            int slot = tid + i * 256;
            int r   = slot >> 4;
            int c16 = slot & 15;
            unsigned dw = (unsigned)__cvta_generic_to_shared(&Ws[r * SROW + c16 * 8]);
            asm volatile("cp.async.ca.shared.global [%0], [%1], 16;"
                         :: "r"(dw), "l"(Wg + r * 128 + c16 * 8));
        }
        asm volatile("cp.async.commit_group;");

        const float4* X4 = (const float4*)x;
#pragma unroll
        for (int i = 0; i < 8; i++) {
            int slot = tid + i * 256;
            int r   = slot >> 4;
            int c16 = slot & 15;
            int gr = row0 + r;
            float4 v0 = make_float4(0.f, 0.f, 0.f, 0.f);
            float4 v1 = v0;
            if (gr < n) {
                v0 = X4[(long long)gr * 32 + c16 * 2];
                v1 = X4[(long long)gr * 32 + c16 * 2 + 1];
            }
            uint4 d;
            *(__half2*)&d.x = __floats2half2_rn(v0.x, v0.y);
            *(__half2*)&d.y = __floats2half2_rn(v0.z, v0.w);
            *(__half2*)&d.z = __floats2half2_rn(v1.x, v1.y);
            *(__half2*)&d.w = __floats2half2_rn(v1.z, v1.w);
            *(uint4*)&As[r * SROW + c16 * 8] = d;
        }
        asm volatile("cp.async.wait_group 0;");
        __syncthreads();

#pragma unroll
        for (int ks = 0; ks < 8; ks++) {
            unsigned a[4][4], b[2][4];
#pragma unroll
            for (int mt = 0; mt < 4; mt++)
                asm volatile(
                    "ldmatrix.sync.aligned.m8n8.x4.shared.b16 {%0,%1,%2,%3}, [%4];"
                    : "=r"(a[mt][0]), "=r"(a[mt][1]), "=r"(a[mt][2]), "=r"(a[mt][3])
                    : "r"(a_base[mt] + ks * 32));
#pragma unroll
            for (int nt2 = 0; nt2 < 2; nt2++)
                asm volatile(
                    "ldmatrix.sync.aligned.m8n8.x4.trans.shared.b16 {%0,%1,%2,%3}, [%4];"
                    : "=r"(b[nt2][0]), "=r"(b[nt2][1]), "=r"(b[nt2][2]), "=r"(b[nt2][3])
                    : "r"(b_base[nt2] + ks * 16 * SROW * 2));
#pragma unroll
            for (int nt2 = 0; nt2 < 2; nt2++)
#pragma unroll
                for (int h8 = 0; h8 < 2; h8++) {
                    int j = nt2 * 2 + h8;
#pragma unroll
                    for (int mt = 0; mt < 4; mt++)
                        asm volatile(
                            "mma.sync.aligned.m16n8k16.row.col.f32.f16.f16.f32 "
                            "{%0,%1,%2,%3}, {%4,%5,%6,%7}, {%8,%9}, {%0,%1,%2,%3};"
                            : "+f"(acc[mt][j][0]), "+f"(acc[mt][j][1]),
                              "+f"(acc[mt][j][2]), "+f"(acc[mt][j][3])
                            : "r"(a[mt][0]), "r"(a[mt][1]),
                              "r"(a[mt][2]), "r"(a[mt][3]),
                              "r"(b[nt2][h8 * 2]), "r"(b[nt2][h8 * 2 + 1]));
                }
        }
    } else {
        const __half* Ag = g_h2;
#pragma unroll
        for (int grp = 0; grp < 2; grp++) {
#pragma unroll
            for (int i = 0; i < 4; i++) {
                int slot = tid + i * 256;       // 0..1023
                int r   = slot >> 3;            // 0..127
                int c16 = (slot & 7) + grp * 8;
                unsigned da = (unsigned)__cvta_generic_to_shared(&As[r * SROW + c16 * 8]);
                const __half* sa = Ag + (long long)(row0 + r) * 128 + c16 * 8;
                int va = (row0 + r < n) ? 16 : 0;
                asm volatile("cp.async.ca.shared.global [%0], [%1], 16, %2;"
                             :: "r"(da), "l"(sa), "r"(va));
                int wrow = grp * 64 + (slot >> 4);
                int wchk = slot & 15;
                unsigned dw = (unsigned)__cvta_generic_to_shared(&Ws[wrow * SROW + wchk * 8]);
                asm volatile("cp.async.ca.shared.global [%0], [%1], 16;"
                             :: "r"(dw), "l"(Wg + wrow * 128 + wchk * 8));
            }
            asm volatile("cp.async.commit_group;");
        }

        asm volatile("cp.async.wait_group 1;");
        __syncthreads();
#pragma unroll
        for (int ks = 0; ks < 4; ks++) {
            unsigned a[4][4], b[2][4];
#pragma unroll
            for (int mt = 0; mt < 4; mt++)
                asm volatile(
                    "ldmatrix.sync.aligned.m8n8.x4.shared.b16 {%0,%1,%2,%3}, [%4];"
                    : "=r"(a[mt][0]), "=r"(a[mt][1]), "=r"(a[mt][2]), "=r"(a[mt][3])
                    : "r"(a_base[mt] + ks * 32));
#pragma unroll
            for (int nt2 = 0; nt2 < 2; nt2++)
                asm volatile(
                    "ldmatrix.sync.aligned.m8n8.x4.trans.shared.b16 {%0,%1,%2,%3}, [%4];"
                    : "=r"(b[nt2][0]), "=r"(b[nt2][1]), "=r"(b[nt2][2]), "=r"(b[nt2][3])
                    : "r"(b_base[nt2] + ks * 16 * SROW * 2));
#pragma unroll
            for (int nt2 = 0; nt2 < 2; nt2++)
#pragma unroll
                for (int h8 = 0; h8 < 2; h8++) {
                    int j = nt2 * 2 + h8;
#pragma unroll
                    for (int mt = 0; mt < 4; mt++)
                        asm volatile(
                            "mma.sync.aligned.m16n8k16.row.col.f32.f16.f16.f32 "
                            "{%0,%1,%2,%3}, {%4,%5,%6,%7}, {%8,%9}, {%0,%1,%2,%3};"
                            : "+f"(acc[mt][j][0]), "+f"(acc[mt][j][1]),
                              "+f"(acc[mt][j][2]), "+f"(acc[mt][j][3])
                            : "r"(a[mt][0]), "r"(a[mt][1]),
                              "r"(a[mt][2]), "r"(a[mt][3]),
                              "r"(b[nt2][h8 * 2]), "r"(b[nt2][h8 * 2 + 1]));
                }
        }
        asm volatile("cp.async.wait_group 0;");
        __syncthreads();
#pragma unroll
        for (int ks = 4; ks < 8; ks++) {
            unsigned a[4][4], b[2][4];
#pragma unroll
            for (int mt = 0; mt < 4; mt++)
                asm volatile(
                    "ldmatrix.sync.aligned.m8n8.x4.shared.b16 {%0,%1,%2,%3}, [%4];"
                    : "=r"(a[mt][0]), "=r"(a[mt][1]), "=r"(a[mt][2]), "=r"(a[mt][3])
                    : "r"(a_base[mt] + ks * 32));
#pragma unroll
            for (int nt2 = 0; nt2 < 2; nt2++)
                asm volatile(
                    "ldmatrix.sync.aligned.m8n8.x4.trans.shared.b16 {%0,%1,%2,%3}, [%4];"
                    : "=r"(b[nt2][0]), "=r"(b[nt2][1]), "=r"(b[nt2][2]), "=r"(b[nt2][3])
                    : "r"(b_base[nt2] + ks * 16 * SROW * 2));
#pragma unroll
            for (int nt2 = 0; nt2 < 2; nt2++)
#pragma unroll
                for (int h8 = 0; h8 < 2; h8++) {
                    int j = nt2 * 2 + h8;
#pragma unroll
                    for (int mt = 0; mt < 4; mt++)
                        asm volatile(
                            "mma.sync.aligned.m16n8k16.row.col.f32.f16.f16.f32 "
                            "{%0,%1,%2,%3}, {%4,%5,%6,%7}, {%8,%9}, {%0,%1,%2,%3};"
                            : "+f"(acc[mt][j][0]), "+f"(acc[mt][j][1]),
                              "+f"(acc[mt][j][2]), "+f"(acc[mt][j][3])
                            : "r"(a[mt][0]), "r"(a[mt][1]),
                              "r"(a[mt][2]), "r"(a[mt][3]),
                              "r"(b[nt2][h8 * 2]), "r"(b[nt2][h8 * 2 + 1]));
                }
        }
    }

    // epilogue: dinv = rsqrt(cnt+1), convert to fp16, write g_half
#pragma unroll
    for (int mt = 0; mt < 4; mt++) {
        int rlo = row0 + warp_m * 64 + mt * 16 + gq;
        int rhi = rlo + 8;
        float dlo = (rlo < n) ? rsqrtf((float)g_cnt[rlo] + 1.0f) : 0.f;
        float dhi = (rhi < n) ? rsqrtf((float)g_cnt[rhi] + 1.0f) : 0.f;
#pragma unroll
        for (int j = 0; j < 4; j++) {
            int c = warp_n * 32 + j * 8 + 2 * tq;
            if (rlo < n)
                *(__half2*)&g_half[rlo * 128 + c] =
                    __floats2half2_rn(acc[mt][j][0] * dlo, acc[mt][j][1] * dlo);
            if (rhi < n)
                *(__half2*)&g_half[rhi * 128 + c] =
                    __floats2half2_rn(acc[mt][j][2] * dhi, acc[mt][j][3] * dhi);
        }
    }
}

// ---------------------------------------------------------------------------
// Aggregate (warp per node):
//   FINAL=0: h=relu(dinv*acc+b) -> g_h2 (fp16)
//   FINAL=1: fused FC + log_softmax -> out
// ---------------------------------------------------------------------------
template <int FINAL>
__global__ void k_agg(const float* __restrict__ b,
                      const float* __restrict__ Wfc,
                      const float* __restrict__ bfc,
                      float* __restrict__ out,
                      int n) {
    int widx = (blockIdx.x * blockDim.x + threadIdx.x) >> 5;
    int q = threadIdx.x & 31;
    if (widx >= n) return;

    float4 acc = gather_node((const uint2*)g_half, widx, q);

    float dv = rsqrtf((float)g_cnt[widx] + 1.0f);
    float4 bb = ((const float4*)b)[q];
    float4 h;
    h.x = fmaxf(dv * acc.x + bb.x, 0.f);
    h.y = fmaxf(dv * acc.y + bb.y, 0.f);
    h.z = fmaxf(dv * acc.z + bb.z, 0.f);
    h.w = fmaxf(dv * acc.w + bb.w, 0.f);

    if (!FINAL) {
        uint2 st;
        *(__half2*)&st.x = __floats2half2_rn(h.x, h.y);
        *(__half2*)&st.y = __floats2half2_rn(h.z, h.w);
        ((uint2*)g_h2)[widx * 32 + q] = st;
    } else {
        const float4* w4 = (const float4*)Wfc;
        float4 w0 = w4[q * 2];
        float4 w1 = w4[q * 2 + 1];
        float l0 = h.x * w0.x + h.y * w0.z + h.z * w1.x + h.w * w1.z;
        float l1 = h.x * w0.y + h.y * w0.w + h.z * w1.y + h.w * w1.w;
#pragma unroll
        for (int o = 16; o > 0; o >>= 1) {
            l0 += __shfl_xor_sync(0xffffffffu, l0, o);
            l1 += __shfl_xor_sync(0xffffffffu, l1, o);
        }
        if (q == 0) {
            l0 += bfc[0];
            l1 += bfc[1];
            float m = fmaxf(l0, l1);
            float z = m + logf(expf(l0 - m) + expf(l1 - m));
            out[widx * 2]     = l0 - z;
            out[widx * 2 + 1] = l1 - z;
        }
    }
}

// ---------------------------------------------------------------------------
extern "C" void kernel_launch(void* const* d_in, const int* in_sizes, int n_in,
                              void* d_out, int out_size) {
    const float* x   = (const float*)d_in[0];
    const void*  ei  = d_in[1];
    const float* W1  = (const float*)d_in[2];
    const float* b1  = (const float*)d_in[3];
    const float* W2  = (const float*)d_in[4];
    const float* b2  = (const float*)d_in[5];
    const float* Wfc = (const float*)d_in[6];
    const float* bfc = (const float*)d_in[7];
    float*       out = (float*)d_out;

    int n = in_sizes[0] / FEAT;
    int E = in_sizes[1] / 2;

    int tb = 256;
    int node_blocks = (n + tb - 1) / tb;
    int edge_blocks = (E + tb - 1) / tb;
    int gemm_blocks = (n + 127) / 128;
    int warp_blocks = (int)(((long long)n * 32 + tb - 1) / tb);

    static int once = 0;
    static cudaStream_t s2;
    static cudaEvent_t ev_fork, ev_join;
    int gemm_smem = 2 * 128 * SROW * (int)sizeof(__half);   // 69632
    if (!once) {
        cudaFuncSetAttribute(k_gemm_f16,
                             cudaFuncAttributeMaxDynamicSharedMemorySize, gemm_smem);
        cudaStreamCreateWithFlags(&s2, cudaStreamNonBlocking);
        cudaEventCreateWithFlags(&ev_fork, cudaEventDisableTiming);
        cudaEventCreateWithFlags(&ev_join, cudaEventDisableTiming);
        once = 1;
    }

    // main stream: init (cnt zero + dtype + W fp16) + histogram
    k_init<<<node_blocks, tb>>>(ei, W1, W2, n);
    k_hist<<<edge_blocks, tb>>>(ei, E);

    // fork: CSR finalize on s2, concurrent with layer-1 GEMM
    cudaEventRecord(ev_fork, 0);
    cudaStreamWaitEvent(s2, ev_fork, 0);
    k_scan1<<<NBLK_SCAN, SCAN_B, 0, s2>>>(n);
    k_scan2<<<1, 512, 0, s2>>>();
    k_scan3<<<node_blocks, tb, 0, s2>>>(n);
    k_place<<<edge_blocks, tb, 0, s2>>>(ei, E);
    cudaEventRecord(ev_join, s2);

    // main: layer-1 GEMM (needs g_cnt + g_w1h)
    k_gemm_f16<<<gemm_blocks, tb, gemm_smem>>>(x, n, 0);

    // join: aggregate needs both CSR and g_half
    cudaStreamWaitEvent(0, ev_join, 0);
    k_agg<0><<<warp_blocks, tb>>>(b1, nullptr, nullptr, nullptr, n);

    // layer 2 + fused FC/log_softmax
    k_gemm_f16<<<gemm_blocks, tb, gemm_smem>>>(x, n, 1);
    k_agg<1><<<warp_blocks, tb>>>(b2, Wfc, bfc, out, n);
}